// round 5
// baseline (speedup 1.0000x reference)
#include <cuda_runtime.h>
#include <cuda_bf16.h>
#include <math.h>

#define NNODE 5000
#define NEDGE 50000
#define FDIM 64

// ---------------- device scratch ----------------
__device__ float g0buf[NNODE * 64];
__device__ float g1buf[NNODE * 192];   // [n][c(3)][f(64)]
__device__ float g2buf[NNODE * 320];   // [n][c(5)][f(64)]
__device__ float abuf[NNODE * 2752];   // [n][ a0(192) | a1(960) | a2(1600) ]
__device__ float d_CG[504];
__device__ int   rcount[NNODE];
__device__ int   rcursor[NNODE];
__device__ int   eperm[NEDGE];

#define OFF110 0
#define OFF220 9
#define OFF121 34
#define OFF211 79
#define OFF231 124
#define OFF112 229
#define OFF132 274
#define OFF222 379

// ---------------- CG coefficient computation (exact, device-side) ----------------
__device__ __forceinline__ double dfact(int n) {
    const double F[10] = {1., 1., 2., 6., 24., 120., 720., 5040., 40320., 362880.};
    return F[n];
}

__device__ double cgc(int j1, int m1, int j2, int m2, int j3, int m3) {
    if (m1 + m2 != m3) return 0.0;
    int lo = j1 - j2; if (lo < 0) lo = -lo;
    if (j3 < lo || j3 > j1 + j2) return 0.0;
    double pref = sqrt((2.0 * j3 + 1.0) * dfact(j3 + j1 - j2) * dfact(j3 - j1 + j2) *
                       dfact(j1 + j2 - j3) / dfact(j1 + j2 + j3 + 1));
    pref *= sqrt(dfact(j3 + m3) * dfact(j3 - m3) * dfact(j1 - m1) * dfact(j1 + m1) *
                 dfact(j2 - m2) * dfact(j2 + m2));
    double s = 0.0;
    for (int k = 0; k <= j1 + j2 + j3; k++) {
        int d0 = j1 + j2 - j3 - k, d1 = j1 - m1 - k, d2 = j2 + m2 - k;
        int d3 = j3 - j2 + m1 + k, d4 = j3 - j1 - m2 + k;
        if (d0 < 0 || d1 < 0 || d2 < 0 || d3 < 0 || d4 < 0) continue;
        double term = 1.0 / (dfact(k) * dfact(d0) * dfact(d1) * dfact(d2) * dfact(d3) * dfact(d4));
        s += (k & 1) ? -term : term;
    }
    return pref * s;
}

__device__ double2 Umat(int l, int i, int a) {
    const double s = 0.70710678118654752440;
    int mi = i - l;
    if (mi == 0) return (a == l) ? make_double2(1.0, 0.0) : make_double2(0.0, 0.0);
    if (mi > 0) {
        int m = mi; double sgn = (m & 1) ? -1.0 : 1.0;
        if (a == l + m) return make_double2(sgn * s, 0.0);
        if (a == l - m) return make_double2(s, 0.0);
    } else {
        int m = -mi; double sgn = (m & 1) ? -1.0 : 1.0;
        if (a == l - m) return make_double2(0.0, s);
        if (a == l + m) return make_double2(0.0, -sgn * s);
    }
    return make_double2(0.0, 0.0);
}

__device__ float realcg(int l1, int l2, int l3, int i, int j, int k) {
    double re = 0.0;
    int d1 = 2 * l1 + 1, d2 = 2 * l2 + 1, d3 = 2 * l3 + 1;
    for (int a = 0; a < d1; a++) {
        double2 u1 = Umat(l1, i, a);
        if (u1.x == 0.0 && u1.y == 0.0) continue;
        for (int b = 0; b < d2; b++) {
            double2 u2 = Umat(l2, j, b);
            if (u2.x == 0.0 && u2.y == 0.0) continue;
            double pr = u1.x * u2.x - u1.y * u2.y;
            double pi = u1.x * u2.y + u1.y * u2.x;
            for (int c = 0; c < d3; c++) {
                double2 u3 = Umat(l3, k, c);
                u3.y = -u3.y;
                if (u3.x == 0.0 && u3.y == 0.0) continue;
                double cg = cgc(l1, a - l1, l2, b - l2, l3, c - l3);
                if (cg == 0.0) continue;
                re += (pr * u3.x - pi * u3.y) * cg;
            }
        }
    }
    return (float)re;
}

__global__ void cg_init_kernel() {
    int idx = blockIdx.x * blockDim.x + threadIdx.x;
    if (idx >= 504) return;
    int l1, l2, l3, flat;
    if (idx < 9)        { l1 = 1; l2 = 1; l3 = 0; flat = idx; }
    else if (idx < 34)  { l1 = 2; l2 = 2; l3 = 0; flat = idx - 9; }
    else if (idx < 79)  { l1 = 1; l2 = 2; l3 = 1; flat = idx - 34; }
    else if (idx < 124) { l1 = 2; l2 = 1; l3 = 1; flat = idx - 79; }
    else if (idx < 229) { l1 = 2; l2 = 3; l3 = 1; flat = idx - 124; }
    else if (idx < 274) { l1 = 1; l2 = 1; l3 = 2; flat = idx - 229; }
    else if (idx < 379) { l1 = 1; l2 = 3; l3 = 2; flat = idx - 274; }
    else                { l1 = 2; l2 = 2; l3 = 2; flat = idx - 379; }
    int dd2 = 2 * l2 + 1, dd3 = 2 * l3 + 1;
    int i = flat / (dd2 * dd3), j = (flat / dd3) % dd2, k = flat % dd3;
    d_CG[idx] = realcg(l1, l2, l3, i, j, k);
}

// ---------------- zero accumulators + histogram counters ----------------
__global__ void zero_acc_kernel() {
    float4* p = reinterpret_cast<float4*>(abuf);
    int n4 = NNODE * 2752 / 4;
    int i = blockIdx.x * blockDim.x + threadIdx.x;
    int stride = gridDim.x * blockDim.x;
    float4 z = make_float4(0.f, 0.f, 0.f, 0.f);
    for (int k = i; k < n4; k += stride) p[k] = z;
    for (int k = i; k < NNODE; k += stride) rcount[k] = 0;
}

// ---------------- counting sort of edges by receiver ----------------
__global__ void hist_kernel(const int* __restrict__ receivers) {
    int e = blockIdx.x * blockDim.x + threadIdx.x;
    if (e < NEDGE) atomicAdd(&rcount[receivers[e]], 1);
}

__global__ void scan_kernel() {
    __shared__ int ssum[1024];
    int t = threadIdx.x;
    const int CH = (NNODE + 1023) / 1024;
    int base = t * CH;
    int s = 0;
    for (int i = 0; i < CH; i++) {
        int idx = base + i;
        if (idx < NNODE) s += rcount[idx];
    }
    ssum[t] = s;
    __syncthreads();
    for (int d = 1; d < 1024; d <<= 1) {
        int v = (t >= d) ? ssum[t - d] : 0;
        __syncthreads();
        ssum[t] += v;
        __syncthreads();
    }
    int run = (t == 0) ? 0 : ssum[t - 1];
    for (int i = 0; i < CH; i++) {
        int idx = base + i;
        if (idx < NNODE) {
            rcursor[idx] = run;
            run += rcount[idx];
        }
    }
}

__global__ void fill_kernel(const int* __restrict__ receivers) {
    int e = blockIdx.x * blockDim.x + threadIdx.x;
    if (e < NEDGE) {
        int pos = atomicAdd(&rcursor[receivers[e]], 1);
        eperm[pos] = e;
    }
}

// ---------------- node prep: sc (-> out) and g projections ----------------
__global__ void node_prep_kernel(const float* __restrict__ nf,
                                 const int* __restrict__ specie,
                                 const float* __restrict__ Wsc0, const float* __restrict__ Wsc1,
                                 const float* __restrict__ Wsc2, const float* __restrict__ Wu0,
                                 const float* __restrict__ Wu1, const float* __restrict__ Wu2,
                                 float* __restrict__ out) {
    int n = blockIdx.x;
    int g = threadIdx.x;  // 64 threads
    __shared__ float sf[576];
    for (int i = g; i < 576; i += 64) sf[i] = nf[n * 576 + i];
    __syncthreads();
    int sp = specie[n];
    const float* w0p = Wsc0 + sp * 4096;
    const float* w1p = Wsc1 + sp * 4096;
    const float* w2p = Wsc2 + sp * 4096;

    float sc0 = 0.f, g0 = 0.f;
    float sc1[3] = {0.f, 0.f, 0.f}, g1[3] = {0.f, 0.f, 0.f};
    float sc2[5] = {0.f, 0.f, 0.f, 0.f, 0.f}, g2[5] = {0.f, 0.f, 0.f, 0.f, 0.f};
#pragma unroll 4
    for (int f = 0; f < 64; f++) {
        float w0 = w0p[f * 64 + g], u0 = Wu0[f * 64 + g];
        float w1 = w1p[f * 64 + g], u1 = Wu1[f * 64 + g];
        float w2 = w2p[f * 64 + g], u2 = Wu2[f * 64 + g];
        float v0 = sf[f];
        sc0 = fmaf(v0, w0, sc0);
        g0  = fmaf(v0, u0, g0);
#pragma unroll
        for (int c = 0; c < 3; c++) {
            float v = sf[64 + f * 3 + c];
            sc1[c] = fmaf(v, w1, sc1[c]);
            g1[c]  = fmaf(v, u1, g1[c]);
        }
#pragma unroll
        for (int c = 0; c < 5; c++) {
            float v = sf[256 + f * 5 + c];
            sc2[c] = fmaf(v, w2, sc2[c]);
            g2[c]  = fmaf(v, u2, g2[c]);
        }
    }
    const float invF = 0.125f;
    float* orow = out + (size_t)n * 576;
    orow[g] = sc0 * invF;
#pragma unroll
    for (int c = 0; c < 3; c++) orow[64 + g * 3 + c] = sc1[c] * invF;
#pragma unroll
    for (int c = 0; c < 5; c++) orow[256 + g * 5 + c] = sc2[c] * invF;
    g0buf[n * 64 + g] = g0 * invF;
#pragma unroll
    for (int c = 0; c < 3; c++) g1buf[n * 192 + c * 64 + g] = g1[c] * invF;
#pragma unroll
    for (int c = 0; c < 5; c++) g2buf[n * 320 + c * 64 + g] = g2[c] * invF;
}

__device__ __forceinline__ float swishf(float x) {
    return x / (1.0f + __expf(-x));
}

// aggregated atomic flush over a group's 4 receiver-sorted edges
__device__ __forceinline__ void agg_atomic(const int* __restrict__ rn4,
                                           const int* __restrict__ act4,
                                           float* const* __restrict__ ap,
                                           int off, const float* __restrict__ v) {
    float acc = 0.f;
#pragma unroll
    for (int el = 0; el < 4; el++) {
        if (act4[el]) acc += v[el];
        bool flush = (el == 3) || (rn4[el + 1] != rn4[el]);
        if (flush) {
            if (acc != 0.f) atomicAdd(ap[el] + off, acc);
            acc = 0.f;
        }
    }
}

// ---------------- edge kernel: 16 sorted edges / block, 256 threads ----------------
__global__ void __launch_bounds__(256) edge_kernel(const float* __restrict__ vectors,
                            const int* __restrict__ senders,
                            const int* __restrict__ receivers,
                            const float* __restrict__ Wm1,
                            const float* __restrict__ Wm2,
                            const float* __restrict__ Wm3) {
    __shared__ float h1[64 * 20];
    __shared__ float h2[64 * 20];
    __shared__ float sT[16 * 104];
    __shared__ float ssh[16 * 16];
    __shared__ float sradT[8 * 16];
    __shared__ float sx[16], sinvx[16];
    __shared__ int ssend[16], srn[16], sact[16];

    int t = threadIdx.x;
    int ft = t & 63;
    int g = t >> 6;       // group g handles sorted edges 4g..4g+3
    int e0 = blockIdx.x * 16;

    // ---- geometry (sorted edge ids) ----
    if (t < 16) {
        int e = eperm[e0 + t];
        float vx = vectors[e * 3 + 0], vy = vectors[e * 3 + 1], vz = vectors[e * 3 + 2];
        float x = sqrtf(fmaxf(vx * vx + vy * vy + vz * vz, 1e-12f));
        float invx = 1.0f / x;
        float ux = vx * invx, uy = vy * invx, uz = vz * invx;
        sx[t] = x; sinvx[t] = invx;
        sact[t] = (x < 1.0f) ? 1 : 0;
        ssend[t] = senders[e];
        srn[t] = receivers[e];
        float* sh = ssh + t * 16;
        const float s3 = 1.7320508075688772f;
        const float s15 = 3.872983346207417f;
        const float s5 = 2.23606797749979f;
        const float c35 = 2.091650066335189f;
        const float c105 = 10.246950765959598f;
        const float c21 = 1.6201851746019651f;
        const float c7 = 1.3228756555322954f;
        sh[0] = s3 * uy; sh[1] = s3 * uz; sh[2] = s3 * ux;
        sh[3] = s15 * ux * uy;
        sh[4] = s15 * uy * uz;
        sh[5] = 0.5f * s5 * (3.0f * uz * uz - 1.0f);
        sh[6] = s15 * ux * uz;
        sh[7] = 0.5f * s15 * (ux * ux - uy * uy);
        sh[8]  = c35 * uy * (3.0f * ux * ux - uy * uy);
        sh[9]  = c105 * ux * uy * uz;
        sh[10] = c21 * uy * (5.0f * uz * uz - 1.0f);
        sh[11] = c7 * uz * (5.0f * uz * uz - 3.0f);
        sh[12] = c21 * ux * (5.0f * uz * uz - 1.0f);
        sh[13] = 0.5f * c105 * uz * (ux * ux - uy * uy);
        sh[14] = c35 * ux * (ux * ux - 3.0f * uy * uy);
        sh[15] = 0.f;
    }
    __syncthreads();

    // ---- radial basis ----
    if (t < 128) {
        int e = t & 15, n = t >> 4;
        float x = sx[e];
        float env = 0.f;
        if (x < 1.0f) {
            float x2 = x * x, x4 = x2 * x2, x6 = x4 * x2, x7 = x6 * x, x8 = x7 * x;
            env = 1.0f - 28.0f * x6 + 48.0f * x7 - 21.0f * x8;
        }
        float nn = (float)(n + 1);
        sradT[n * 16 + e] = 1.41421356237f * sinf(3.14159265358979f * nn * x) * sinvx[e] * env;
    }
    __syncthreads();

    // ---- contracted CG tensors ----
    for (int idx = t; idx < 16 * 102; idx += 256) {
        int e = idx / 102, j = idx % 102;
        const float* sh = ssh + e * 16;
        float v = 0.f;
        if (j < 3) {
            int i = j;
            for (int q = 0; q < 3; q++) v = fmaf(sh[q], d_CG[OFF110 + i * 3 + q], v);
        } else if (j < 8) {
            int i = j - 3;
            for (int q = 0; q < 5; q++) v = fmaf(sh[3 + q], d_CG[OFF220 + i * 5 + q], v);
        } else if (j < 17) {
            int ee = j - 8; int i = ee / 3, k = ee % 3;
            for (int q = 0; q < 5; q++) v = fmaf(sh[3 + q], d_CG[OFF121 + (i * 5 + q) * 3 + k], v);
        } else if (j < 32) {
            int ee = j - 17; int i = ee / 3, k = ee % 3;
            for (int q = 0; q < 3; q++) v = fmaf(sh[q], d_CG[OFF211 + (i * 3 + q) * 3 + k], v);
        } else if (j < 47) {
            int ee = j - 32; int i = ee / 3, k = ee % 3;
            for (int q = 0; q < 7; q++) v = fmaf(sh[8 + q], d_CG[OFF231 + (i * 7 + q) * 3 + k], v);
        } else if (j < 62) {
            int ee = j - 47; int i = ee / 5, k = ee % 5;
            for (int q = 0; q < 3; q++) v = fmaf(sh[q], d_CG[OFF112 + (i * 3 + q) * 5 + k], v);
        } else if (j < 77) {
            int ee = j - 62; int i = ee / 5, k = ee % 5;
            for (int q = 0; q < 7; q++) v = fmaf(sh[8 + q], d_CG[OFF132 + (i * 7 + q) * 5 + k], v);
        } else {
            int ee = j - 77; int i = ee / 5, k = ee % 5;
            for (int q = 0; q < 5; q++) v = fmaf(sh[3 + q], d_CG[OFF222 + (i * 5 + q) * 5 + k], v);
        }
        sT[e * 104 + j] = v;
    }
    __syncthreads();

    // ---- MLP layer 1: 8 -> 64 ----
    {
        float a0 = 0.f, a1 = 0.f, a2 = 0.f, a3 = 0.f;
#pragma unroll
        for (int i = 0; i < 8; i++) {
            float w = Wm1[i * 64 + ft];
            float4 r = *(const float4*)(sradT + i * 16 + 4 * g);
            a0 = fmaf(r.x, w, a0); a1 = fmaf(r.y, w, a1);
            a2 = fmaf(r.z, w, a2); a3 = fmaf(r.w, w, a3);
        }
        const float s8 = 0.35355339059327f;
        h1[ft * 20 + 4 * g + 0] = swishf(a0 * s8);
        h1[ft * 20 + 4 * g + 1] = swishf(a1 * s8);
        h1[ft * 20 + 4 * g + 2] = swishf(a2 * s8);
        h1[ft * 20 + 4 * g + 3] = swishf(a3 * s8);
    }
    __syncthreads();

    // ---- MLP layer 2: 64 -> 64 ----
    {
        float a0 = 0.f, a1 = 0.f, a2 = 0.f, a3 = 0.f;
#pragma unroll 8
        for (int f = 0; f < 64; f++) {
            float w = Wm2[f * 64 + ft];
            float4 hv = *(const float4*)(h1 + f * 20 + 4 * g);
            a0 = fmaf(hv.x, w, a0); a1 = fmaf(hv.y, w, a1);
            a2 = fmaf(hv.z, w, a2); a3 = fmaf(hv.w, w, a3);
        }
        const float s64 = 0.125f;
        h2[ft * 20 + 4 * g + 0] = swishf(a0 * s64);
        h2[ft * 20 + 4 * g + 1] = swishf(a1 * s64);
        h2[ft * 20 + 4 * g + 2] = swishf(a2 * s64);
        h2[ft * 20 + 4 * g + 3] = swishf(a3 * s64);
    }
    __syncthreads();

    // ---- gather sender features ----
    float s0v[4], s1v[4][3], s2v[4][5];
    float* ap[4];
#pragma unroll
    for (int el = 0; el < 4; el++) {
        int e = 4 * g + el;
        int sn = ssend[e];
        ap[el] = abuf + (size_t)srn[e] * 2752;
        s0v[el] = g0buf[sn * 64 + ft];
#pragma unroll
        for (int c = 0; c < 3; c++) s1v[el][c] = g1buf[sn * 192 + c * 64 + ft];
#pragma unroll
        for (int c = 0; c < 5; c++) s2v[el][c] = g2buf[sn * 320 + c * 64 + ft];
    }
    const int* rn4 = srn + 4 * g;
    const int* act4 = sact + 4 * g;
    const float msc = 0.125f * 0.316227766016838f;

    float mx[4], v[4];
#define MIX_COMPUTE(M)                                                        \
    {                                                                         \
        float a0 = 0.f, a1 = 0.f, a2 = 0.f, a3 = 0.f;                         \
        const float* wp = Wm3 + (M) * 64 + ft;                                \
        _Pragma("unroll 8")                                                   \
        for (int f = 0; f < 64; f++) {                                        \
            float w = wp[f * 832];                                            \
            float4 hv = *(const float4*)(h2 + f * 20 + 4 * g);                \
            a0 = fmaf(hv.x, w, a0); a1 = fmaf(hv.y, w, a1);                   \
            a2 = fmaf(hv.z, w, a2); a3 = fmaf(hv.w, w, a3);                   \
        }                                                                     \
        mx[0] = a0 * msc; mx[1] = a1 * msc; mx[2] = a2 * msc; mx[3] = a3 * msc; \
    }

    // m=0: a0[0:64] += s0 * mix
    MIX_COMPUTE(0);
#pragma unroll
    for (int el = 0; el < 4; el++) v[el] = s0v[el] * mx[el];
    agg_atomic(rn4, act4, ap, ft, v);

    // m=1: a0[64:128] += tp110 * mix
    MIX_COMPUTE(1);
#pragma unroll
    for (int el = 0; el < 4; el++) {
        const float* T = sT + (4 * g + el) * 104;
        v[el] = (s1v[el][0] * T[0] + s1v[el][1] * T[1] + s1v[el][2] * T[2]) * mx[el];
    }
    agg_atomic(rn4, act4, ap, 64 + ft, v);

    // m=2: a0[128:192] += tp220 * mix
    MIX_COMPUTE(2);
#pragma unroll
    for (int el = 0; el < 4; el++) {
        const float* T = sT + (4 * g + el) * 104;
        float tp = 0.f;
#pragma unroll
        for (int i = 0; i < 5; i++) tp = fmaf(s2v[el][i], T[3 + i], tp);
        v[el] = tp * mx[el];
    }
    agg_atomic(rn4, act4, ap, 128 + ft, v);

    // m=3: a1 block 0: s1[c]
    MIX_COMPUTE(3);
#pragma unroll
    for (int c = 0; c < 3; c++) {
#pragma unroll
        for (int el = 0; el < 4; el++) v[el] = s1v[el][c] * mx[el];
        agg_atomic(rn4, act4, ap, 192 + c * 320 + ft, v);
    }

    // m=4: a1 block 1: s0*sh1[c]
    MIX_COMPUTE(4);
#pragma unroll
    for (int c = 0; c < 3; c++) {
#pragma unroll
        for (int el = 0; el < 4; el++)
            v[el] = s0v[el] * ssh[(4 * g + el) * 16 + c] * mx[el];
        agg_atomic(rn4, act4, ap, 192 + c * 320 + 64 + ft, v);
    }

    // m=5: a1 block 2: t121
    MIX_COMPUTE(5);
#pragma unroll
    for (int c = 0; c < 3; c++) {
#pragma unroll
        for (int el = 0; el < 4; el++) {
            const float* T = sT + (4 * g + el) * 104;
            v[el] = (s1v[el][0] * T[8 + c] + s1v[el][1] * T[11 + c] + s1v[el][2] * T[14 + c]) * mx[el];
        }
        agg_atomic(rn4, act4, ap, 192 + c * 320 + 128 + ft, v);
    }

    // m=6: a1 block 3: t211
    MIX_COMPUTE(6);
#pragma unroll
    for (int c = 0; c < 3; c++) {
#pragma unroll
        for (int el = 0; el < 4; el++) {
            const float* T = sT + (4 * g + el) * 104;
            float tp = 0.f;
#pragma unroll
            for (int i = 0; i < 5; i++) tp = fmaf(s2v[el][i], T[17 + i * 3 + c], tp);
            v[el] = tp * mx[el];
        }
        agg_atomic(rn4, act4, ap, 192 + c * 320 + 192 + ft, v);
    }

    // m=7: a1 block 4: t231
    MIX_COMPUTE(7);
#pragma unroll
    for (int c = 0; c < 3; c++) {
#pragma unroll
        for (int el = 0; el < 4; el++) {
            const float* T = sT + (4 * g + el) * 104;
            float tp = 0.f;
#pragma unroll
            for (int i = 0; i < 5; i++) tp = fmaf(s2v[el][i], T[32 + i * 3 + c], tp);
            v[el] = tp * mx[el];
        }
        agg_atomic(rn4, act4, ap, 192 + c * 320 + 256 + ft, v);
    }

    // m=8: a2 block 0: s2[c]
    MIX_COMPUTE(8);
#pragma unroll
    for (int c = 0; c < 5; c++) {
#pragma unroll
        for (int el = 0; el < 4; el++) v[el] = s2v[el][c] * mx[el];
        agg_atomic(rn4, act4, ap, 1152 + c * 320 + ft, v);
    }

    // m=9: a2 block 1: s0*sh2[c]
    MIX_COMPUTE(9);
#pragma unroll
    for (int c = 0; c < 5; c++) {
#pragma unroll
        for (int el = 0; el < 4; el++)
            v[el] = s0v[el] * ssh[(4 * g + el) * 16 + 3 + c] * mx[el];
        agg_atomic(rn4, act4, ap, 1152 + c * 320 + 64 + ft, v);
    }

    // m=10: a2 block 2: t112
    MIX_COMPUTE(10);
#pragma unroll
    for (int c = 0; c < 5; c++) {
#pragma unroll
        for (int el = 0; el < 4; el++) {
            const float* T = sT + (4 * g + el) * 104;
            float tp = 0.f;
#pragma unroll
            for (int i = 0; i < 3; i++) tp = fmaf(s1v[el][i], T[47 + i * 5 + c], tp);
            v[el] = tp * mx[el];
        }
        agg_atomic(rn4, act4, ap, 1152 + c * 320 + 128 + ft, v);
    }

    // m=11: a2 block 3: t132
    MIX_COMPUTE(11);
#pragma unroll
    for (int c = 0; c < 5; c++) {
#pragma unroll
        for (int el = 0; el < 4; el++) {
            const float* T = sT + (4 * g + el) * 104;
            float tp = 0.f;
#pragma unroll
            for (int i = 0; i < 3; i++) tp = fmaf(s1v[el][i], T[62 + i * 5 + c], tp);
            v[el] = tp * mx[el];
        }
        agg_atomic(rn4, act4, ap, 1152 + c * 320 + 192 + ft, v);
    }

    // m=12: a2 block 4: t222
    MIX_COMPUTE(12);
#pragma unroll
    for (int c = 0; c < 5; c++) {
#pragma unroll
        for (int el = 0; el < 4; el++) {
            const float* T = sT + (4 * g + el) * 104;
            float tp = 0.f;
#pragma unroll
            for (int i = 0; i < 5; i++) tp = fmaf(s2v[el][i], T[77 + i * 5 + c], tp);
            v[el] = tp * mx[el];
        }
        agg_atomic(rn4, act4, ap, 1152 + c * 320 + 256 + ft, v);
    }
#undef MIX_COMPUTE
}

// ---------------- node output: 4 nodes / block, 320 threads ----------------
__global__ void __launch_bounds__(320) node_out_kernel(const float* __restrict__ Wd0,
                                const float* __restrict__ Wd1,
                                const float* __restrict__ Wd2,
                                float* __restrict__ out) {
    int n0 = blockIdx.x * 4;
    int t = threadIdx.x;
    __shared__ float saT[2752 * 4];
    __shared__ float sd0[4 * 192];

    for (int j = t; j < 2752; j += 320) {
#pragma unroll
        for (int nn = 0; nn < 4; nn++)
            saT[j * 4 + nn] = abuf[(size_t)(n0 + nn) * 2752 + j];
    }
    __syncthreads();

    if (t < 192) {
        float a0 = 0.f, a1 = 0.f, a2 = 0.f, a3 = 0.f;
#pragma unroll 8
        for (int m = 0; m < 192; m++) {
            float w = Wd0[m * 192 + t];
            float4 av = *(const float4*)(saT + m * 4);
            a0 = fmaf(av.x, w, a0); a1 = fmaf(av.y, w, a1);
            a2 = fmaf(av.z, w, a2); a3 = fmaf(av.w, w, a3);
        }
        const float s = 0.0721687836487032f;
        sd0[0 * 192 + t] = swishf(a0 * s);
        sd0[1 * 192 + t] = swishf(a1 * s);
        sd0[2 * 192 + t] = swishf(a2 * s);
        sd0[3 * 192 + t] = swishf(a3 * s);
    }
    __syncthreads();

    if (t < 64) {
#pragma unroll
        for (int nn = 0; nn < 4; nn++)
            out[(size_t)(n0 + nn) * 576 + t] += sd0[nn * 192 + t];
    }

    const float s320 = 0.0559016994374947f;

    if (t < 192) {
        int c = t / 64, f = t % 64;
        float a0 = 0.f, a1 = 0.f, a2 = 0.f, a3 = 0.f;
        const float* base = saT + (192 + c * 320) * 4;
#pragma unroll 8
        for (int m = 0; m < 320; m++) {
            float w = Wd1[m * 64 + f];
            float4 av = *(const float4*)(base + m * 4);
            a0 = fmaf(av.x, w, a0); a1 = fmaf(av.y, w, a1);
            a2 = fmaf(av.z, w, a2); a3 = fmaf(av.w, w, a3);
        }
        float r[4] = {a0, a1, a2, a3};
#pragma unroll
        for (int nn = 0; nn < 4; nn++)
            out[(size_t)(n0 + nn) * 576 + 64 + f * 3 + c] += r[nn] * s320 * sd0[nn * 192 + 64 + f];
    }

    {
        int c = t / 64, f = t % 64;
        float a0 = 0.f, a1 = 0.f, a2 = 0.f, a3 = 0.f;
        const float* base = saT + (1152 + c * 320) * 4;
#pragma unroll 8
        for (int m = 0; m < 320; m++) {
            float w = Wd2[m * 64 + f];
            float4 av = *(const float4*)(base + m * 4);
            a0 = fmaf(av.x, w, a0); a1 = fmaf(av.y, w, a1);
            a2 = fmaf(av.z, w, a2); a3 = fmaf(av.w, w, a3);
        }
        float r[4] = {a0, a1, a2, a3};
#pragma unroll
        for (int nn = 0; nn < 4; nn++)
            out[(size_t)(n0 + nn) * 576 + 256 + f * 5 + c] += r[nn] * s320 * sd0[nn * 192 + 128 + f];
    }
}

// ---------------- launcher ----------------
extern "C" void kernel_launch(void* const* d_in, const int* in_sizes, int n_in,
                              void* d_out, int out_size) {
    const float* vectors    = (const float*)d_in[0];
    const float* node_feats = (const float*)d_in[1];
    const int*   node_specie= (const int*)d_in[2];
    const int*   senders    = (const int*)d_in[3];
    const int*   receivers  = (const int*)d_in[4];
    const float* Wsc0 = (const float*)d_in[5];
    const float* Wsc1 = (const float*)d_in[6];
    const float* Wsc2 = (const float*)d_in[7];
    const float* Wu0  = (const float*)d_in[8];
    const float* Wu1  = (const float*)d_in[9];
    const float* Wu2  = (const float*)d_in[10];
    const float* Wm1  = (const float*)d_in[11];
    const float* Wm2  = (const float*)d_in[12];
    const float* Wm3  = (const float*)d_in[13];
    const float* Wd0  = (const float*)d_in[14];
    const float* Wd1  = (const float*)d_in[15];
    const float* Wd2  = (const float*)d_in[16];
    float* out = (float*)d_out;

    cg_init_kernel<<<16, 32>>>();
    zero_acc_kernel<<<2048, 256>>>();
    hist_kernel<<<(NEDGE + 255) / 256, 256>>>(receivers);
    scan_kernel<<<1, 1024>>>();
    fill_kernel<<<(NEDGE + 255) / 256, 256>>>(receivers);
    node_prep_kernel<<<NNODE, 64>>>(node_feats, node_specie, Wsc0, Wsc1, Wsc2,
                                    Wu0, Wu1, Wu2, out);
    edge_kernel<<<NEDGE / 16, 256>>>(vectors, senders, receivers, Wm1, Wm2, Wm3);
    node_out_kernel<<<NNODE / 4, 320>>>(Wd0, Wd1, Wd2, out);
}

// round 6
// speedup vs baseline: 1.2427x; 1.2427x over previous
#include <cuda_runtime.h>
#include <cuda_bf16.h>
#include <math.h>

#define NNODE 5000
#define NEDGE 50000
#define FDIM 64

// ---------------- device scratch ----------------
__device__ float g0buf[NNODE * 64];
__device__ float g1buf[NNODE * 192];   // [n][c(3)][f(64)]
__device__ float g2buf[NNODE * 320];   // [n][c(5)][f(64)]
__device__ float abuf[NNODE * 2752];   // [n][ a0(192) | a1(960) | a2(1600) ]
__device__ float d_CG[504];

#define OFF110 0
#define OFF220 9
#define OFF121 34
#define OFF211 79
#define OFF231 124
#define OFF112 229
#define OFF132 274
#define OFF222 379

// ---------------- CG coefficient computation (exact, device-side) ----------------
__device__ __forceinline__ double dfact(int n) {
    const double F[10] = {1., 1., 2., 6., 24., 120., 720., 5040., 40320., 362880.};
    return F[n];
}

__device__ double cgc(int j1, int m1, int j2, int m2, int j3, int m3) {
    if (m1 + m2 != m3) return 0.0;
    int lo = j1 - j2; if (lo < 0) lo = -lo;
    if (j3 < lo || j3 > j1 + j2) return 0.0;
    double pref = sqrt((2.0 * j3 + 1.0) * dfact(j3 + j1 - j2) * dfact(j3 - j1 + j2) *
                       dfact(j1 + j2 - j3) / dfact(j1 + j2 + j3 + 1));
    pref *= sqrt(dfact(j3 + m3) * dfact(j3 - m3) * dfact(j1 - m1) * dfact(j1 + m1) *
                 dfact(j2 - m2) * dfact(j2 + m2));
    double s = 0.0;
    for (int k = 0; k <= j1 + j2 + j3; k++) {
        int d0 = j1 + j2 - j3 - k, d1 = j1 - m1 - k, d2 = j2 + m2 - k;
        int d3 = j3 - j2 + m1 + k, d4 = j3 - j1 - m2 + k;
        if (d0 < 0 || d1 < 0 || d2 < 0 || d3 < 0 || d4 < 0) continue;
        double term = 1.0 / (dfact(k) * dfact(d0) * dfact(d1) * dfact(d2) * dfact(d3) * dfact(d4));
        s += (k & 1) ? -term : term;
    }
    return pref * s;
}

__device__ double2 Umat(int l, int i, int a) {
    const double s = 0.70710678118654752440;
    int mi = i - l;
    if (mi == 0) return (a == l) ? make_double2(1.0, 0.0) : make_double2(0.0, 0.0);
    if (mi > 0) {
        int m = mi; double sgn = (m & 1) ? -1.0 : 1.0;
        if (a == l + m) return make_double2(sgn * s, 0.0);
        if (a == l - m) return make_double2(s, 0.0);
    } else {
        int m = -mi; double sgn = (m & 1) ? -1.0 : 1.0;
        if (a == l - m) return make_double2(0.0, s);
        if (a == l + m) return make_double2(0.0, -sgn * s);
    }
    return make_double2(0.0, 0.0);
}

__device__ float realcg(int l1, int l2, int l3, int i, int j, int k) {
    double re = 0.0;
    int d1 = 2 * l1 + 1, d2 = 2 * l2 + 1, d3 = 2 * l3 + 1;
    for (int a = 0; a < d1; a++) {
        double2 u1 = Umat(l1, i, a);
        if (u1.x == 0.0 && u1.y == 0.0) continue;
        for (int b = 0; b < d2; b++) {
            double2 u2 = Umat(l2, j, b);
            if (u2.x == 0.0 && u2.y == 0.0) continue;
            double pr = u1.x * u2.x - u1.y * u2.y;
            double pi = u1.x * u2.y + u1.y * u2.x;
            for (int c = 0; c < d3; c++) {
                double2 u3 = Umat(l3, k, c);
                u3.y = -u3.y;
                if (u3.x == 0.0 && u3.y == 0.0) continue;
                double cg = cgc(l1, a - l1, l2, b - l2, l3, c - l3);
                if (cg == 0.0) continue;
                re += (pr * u3.x - pi * u3.y) * cg;
            }
        }
    }
    return (float)re;
}

__global__ void cg_init_kernel() {
    int idx = blockIdx.x * blockDim.x + threadIdx.x;
    if (idx >= 504) return;
    int l1, l2, l3, flat;
    if (idx < 9)        { l1 = 1; l2 = 1; l3 = 0; flat = idx; }
    else if (idx < 34)  { l1 = 2; l2 = 2; l3 = 0; flat = idx - 9; }
    else if (idx < 79)  { l1 = 1; l2 = 2; l3 = 1; flat = idx - 34; }
    else if (idx < 124) { l1 = 2; l2 = 1; l3 = 1; flat = idx - 79; }
    else if (idx < 229) { l1 = 2; l2 = 3; l3 = 1; flat = idx - 124; }
    else if (idx < 274) { l1 = 1; l2 = 1; l3 = 2; flat = idx - 229; }
    else if (idx < 379) { l1 = 1; l2 = 3; l3 = 2; flat = idx - 274; }
    else                { l1 = 2; l2 = 2; l3 = 2; flat = idx - 379; }
    int dd2 = 2 * l2 + 1, dd3 = 2 * l3 + 1;
    int i = flat / (dd2 * dd3), j = (flat / dd3) % dd2, k = flat % dd3;
    d_CG[idx] = realcg(l1, l2, l3, i, j, k);
}

// ---------------- zero accumulators (vectorized) ----------------
__global__ void zero_acc_kernel() {
    float4* p = reinterpret_cast<float4*>(abuf);
    int n4 = NNODE * 2752 / 4;
    int i = blockIdx.x * blockDim.x + threadIdx.x;
    int stride = gridDim.x * blockDim.x;
    float4 z = make_float4(0.f, 0.f, 0.f, 0.f);
    for (int k = i; k < n4; k += stride) p[k] = z;
}

// ---------------- node prep: sc (-> out) and g projections ----------------
__global__ void node_prep_kernel(const float* __restrict__ nf,
                                 const int* __restrict__ specie,
                                 const float* __restrict__ Wsc0, const float* __restrict__ Wsc1,
                                 const float* __restrict__ Wsc2, const float* __restrict__ Wu0,
                                 const float* __restrict__ Wu1, const float* __restrict__ Wu2,
                                 float* __restrict__ out) {
    int n = blockIdx.x;
    int g = threadIdx.x;  // 64 threads
    __shared__ float sf[576];
    for (int i = g; i < 576; i += 64) sf[i] = nf[n * 576 + i];
    __syncthreads();
    int sp = specie[n];
    const float* w0p = Wsc0 + sp * 4096;
    const float* w1p = Wsc1 + sp * 4096;
    const float* w2p = Wsc2 + sp * 4096;

    float sc0 = 0.f, g0 = 0.f;
    float sc1[3] = {0.f, 0.f, 0.f}, g1[3] = {0.f, 0.f, 0.f};
    float sc2[5] = {0.f, 0.f, 0.f, 0.f, 0.f}, g2[5] = {0.f, 0.f, 0.f, 0.f, 0.f};
#pragma unroll 4
    for (int f = 0; f < 64; f++) {
        float w0 = w0p[f * 64 + g], u0 = Wu0[f * 64 + g];
        float w1 = w1p[f * 64 + g], u1 = Wu1[f * 64 + g];
        float w2 = w2p[f * 64 + g], u2 = Wu2[f * 64 + g];
        float v0 = sf[f];
        sc0 = fmaf(v0, w0, sc0);
        g0  = fmaf(v0, u0, g0);
#pragma unroll
        for (int c = 0; c < 3; c++) {
            float v = sf[64 + f * 3 + c];
            sc1[c] = fmaf(v, w1, sc1[c]);
            g1[c]  = fmaf(v, u1, g1[c]);
        }
#pragma unroll
        for (int c = 0; c < 5; c++) {
            float v = sf[256 + f * 5 + c];
            sc2[c] = fmaf(v, w2, sc2[c]);
            g2[c]  = fmaf(v, u2, g2[c]);
        }
    }
    const float invF = 0.125f;
    float* orow = out + (size_t)n * 576;
    orow[g] = sc0 * invF;
#pragma unroll
    for (int c = 0; c < 3; c++) orow[64 + g * 3 + c] = sc1[c] * invF;
#pragma unroll
    for (int c = 0; c < 5; c++) orow[256 + g * 5 + c] = sc2[c] * invF;
    g0buf[n * 64 + g] = g0 * invF;
#pragma unroll
    for (int c = 0; c < 3; c++) g1buf[n * 192 + c * 64 + g] = g1[c] * invF;
#pragma unroll
    for (int c = 0; c < 5; c++) g2buf[n * 320 + c * 64 + g] = g2[c] * invF;
}

__device__ __forceinline__ float swishf(float x) {
    return x / (1.0f + __expf(-x));
}

// ---------------- edge kernel: 16 edges / block, 256 threads (4 groups x 4 edges) ----------------
// dynamic smem layout (floats):
//   smix  [16][13*64]  @ 0      (13312)
//   h1    [64][20]     @ 13312  (1280)
//   h2    [64][20]     @ 14592  (1280)
//   sT    [16][104]    @ 15872  (1664)
//   ssh   [16][16]     @ 17536  (256)
//   sradT [8][16]      @ 17792  (128)
//   sx    [16]         @ 17920
//   sinvx [16]         @ 17936
// total 17952 floats = 71808 B
#define EK_SMEM_FLOATS 17952

__global__ void __launch_bounds__(256) edge_kernel(const float* __restrict__ vectors,
                            const int* __restrict__ senders,
                            const int* __restrict__ receivers,
                            const float* __restrict__ Wm1,
                            const float* __restrict__ Wm2,
                            const float* __restrict__ Wm3) {
    extern __shared__ float sm[];
    float* smix  = sm;
    float* h1    = sm + 13312;
    float* h2    = sm + 14592;
    float* sT    = sm + 15872;
    float* ssh   = sm + 17536;
    float* sradT = sm + 17792;
    float* sx    = sm + 17920;
    float* sinvx = sm + 17936;
    __shared__ int ssend[16], srecv[16], sact[16];

    int t = threadIdx.x;
    int ft = t & 63;
    int g = t >> 6;       // 0..3, group g handles edges 4g..4g+3
    int e0 = blockIdx.x * 16;

    // ---- geometry ----
    if (t < 16) {
        int e = e0 + t;
        float vx = vectors[e * 3 + 0], vy = vectors[e * 3 + 1], vz = vectors[e * 3 + 2];
        float x = sqrtf(fmaxf(vx * vx + vy * vy + vz * vz, 1e-12f));
        float invx = 1.0f / x;
        float ux = vx * invx, uy = vy * invx, uz = vz * invx;
        sx[t] = x; sinvx[t] = invx;
        sact[t] = (x < 1.0f) ? 1 : 0;
        ssend[t] = senders[e];
        srecv[t] = receivers[e];
        float* sh = ssh + t * 16;
        const float s3 = 1.7320508075688772f;
        const float s15 = 3.872983346207417f;
        const float s5 = 2.23606797749979f;
        const float c35 = 2.091650066335189f;
        const float c105 = 10.246950765959598f;
        const float c21 = 1.6201851746019651f;
        const float c7 = 1.3228756555322954f;
        sh[0] = s3 * uy; sh[1] = s3 * uz; sh[2] = s3 * ux;
        sh[3] = s15 * ux * uy;
        sh[4] = s15 * uy * uz;
        sh[5] = 0.5f * s5 * (3.0f * uz * uz - 1.0f);
        sh[6] = s15 * ux * uz;
        sh[7] = 0.5f * s15 * (ux * ux - uy * uy);
        sh[8]  = c35 * uy * (3.0f * ux * ux - uy * uy);
        sh[9]  = c105 * ux * uy * uz;
        sh[10] = c21 * uy * (5.0f * uz * uz - 1.0f);
        sh[11] = c7 * uz * (5.0f * uz * uz - 3.0f);
        sh[12] = c21 * ux * (5.0f * uz * uz - 1.0f);
        sh[13] = 0.5f * c105 * uz * (ux * ux - uy * uy);
        sh[14] = c35 * ux * (ux * ux - 3.0f * uy * uy);
        sh[15] = 0.f;
    }
    __syncthreads();

    // ---- radial basis ----
    if (t < 128) {
        int e = t & 15, n = t >> 4;
        float x = sx[e];
        float env = 0.f;
        if (x < 1.0f) {
            float x2 = x * x, x4 = x2 * x2, x6 = x4 * x2, x7 = x6 * x, x8 = x7 * x;
            env = 1.0f - 28.0f * x6 + 48.0f * x7 - 21.0f * x8;
        }
        float nn = (float)(n + 1);
        sradT[n * 16 + e] = 1.41421356237f * sinf(3.14159265358979f * nn * x) * sinvx[e] * env;
    }
    __syncthreads();

    // ---- contracted CG tensors: sT[e][j] = sum_j' sh[e][j'] * C[i,j',k] ----
    for (int idx = t; idx < 16 * 102; idx += 256) {
        int e = idx / 102, j = idx % 102;
        const float* sh = ssh + e * 16;
        float v = 0.f;
        if (j < 3) {
            int i = j;
            for (int q = 0; q < 3; q++) v = fmaf(sh[q], d_CG[OFF110 + i * 3 + q], v);
        } else if (j < 8) {
            int i = j - 3;
            for (int q = 0; q < 5; q++) v = fmaf(sh[3 + q], d_CG[OFF220 + i * 5 + q], v);
        } else if (j < 17) {
            int ee = j - 8; int i = ee / 3, k = ee % 3;
            for (int q = 0; q < 5; q++) v = fmaf(sh[3 + q], d_CG[OFF121 + (i * 5 + q) * 3 + k], v);
        } else if (j < 32) {
            int ee = j - 17; int i = ee / 3, k = ee % 3;
            for (int q = 0; q < 3; q++) v = fmaf(sh[q], d_CG[OFF211 + (i * 3 + q) * 3 + k], v);
        } else if (j < 47) {
            int ee = j - 32; int i = ee / 3, k = ee % 3;
            for (int q = 0; q < 7; q++) v = fmaf(sh[8 + q], d_CG[OFF231 + (i * 7 + q) * 3 + k], v);
        } else if (j < 62) {
            int ee = j - 47; int i = ee / 5, k = ee % 5;
            for (int q = 0; q < 3; q++) v = fmaf(sh[q], d_CG[OFF112 + (i * 3 + q) * 5 + k], v);
        } else if (j < 77) {
            int ee = j - 62; int i = ee / 5, k = ee % 5;
            for (int q = 0; q < 7; q++) v = fmaf(sh[8 + q], d_CG[OFF132 + (i * 7 + q) * 5 + k], v);
        } else {
            int ee = j - 77; int i = ee / 5, k = ee % 5;
            for (int q = 0; q < 5; q++) v = fmaf(sh[3 + q], d_CG[OFF222 + (i * 5 + q) * 5 + k], v);
        }
        sT[e * 104 + j] = v;
    }
    __syncthreads();

    // ---- MLP layer 1: 8 -> 64 ----
    {
        float a0 = 0.f, a1 = 0.f, a2 = 0.f, a3 = 0.f;
#pragma unroll
        for (int i = 0; i < 8; i++) {
            float w = Wm1[i * 64 + ft];
            float4 r = *(const float4*)(sradT + i * 16 + 4 * g);
            a0 = fmaf(r.x, w, a0); a1 = fmaf(r.y, w, a1);
            a2 = fmaf(r.z, w, a2); a3 = fmaf(r.w, w, a3);
        }
        const float s8 = 0.35355339059327f;
        h1[ft * 20 + 4 * g + 0] = swishf(a0 * s8);
        h1[ft * 20 + 4 * g + 1] = swishf(a1 * s8);
        h1[ft * 20 + 4 * g + 2] = swishf(a2 * s8);
        h1[ft * 20 + 4 * g + 3] = swishf(a3 * s8);
    }
    __syncthreads();

    // ---- MLP layer 2: 64 -> 64 ----
    {
        float a0 = 0.f, a1 = 0.f, a2 = 0.f, a3 = 0.f;
#pragma unroll 8
        for (int f = 0; f < 64; f++) {
            float w = Wm2[f * 64 + ft];
            float4 hv = *(const float4*)(h1 + f * 20 + 4 * g);
            a0 = fmaf(hv.x, w, a0); a1 = fmaf(hv.y, w, a1);
            a2 = fmaf(hv.z, w, a2); a3 = fmaf(hv.w, w, a3);
        }
        const float s64 = 0.125f;
        h2[ft * 20 + 4 * g + 0] = swishf(a0 * s64);
        h2[ft * 20 + 4 * g + 1] = swishf(a1 * s64);
        h2[ft * 20 + 4 * g + 2] = swishf(a2 * s64);
        h2[ft * 20 + 4 * g + 3] = swishf(a3 * s64);
    }
    __syncthreads();

    // ---- MLP layer 3: 64 -> 13*64, register-blocked in two passes ----
    // pass A: m = 0..6  (28 accumulators), pass B: m = 7..12 (24 accumulators)
    // each f-iteration: 1 shared h2 LDS.128 + 7(6) LDG feeding 28(24) FMAs
    {
        const float msc = 0.125f * 0.316227766016838f;  // /sqrt(64) * 1/sqrt(AVG)
        {
            float acc[7][4];
#pragma unroll
            for (int m = 0; m < 7; m++)
#pragma unroll
                for (int el = 0; el < 4; el++) acc[m][el] = 0.f;
#pragma unroll 2
            for (int f = 0; f < 64; f++) {
                float4 hv = *(const float4*)(h2 + f * 20 + 4 * g);
                const float* wrow = Wm3 + f * 832 + ft;
#pragma unroll
                for (int m = 0; m < 7; m++) {
                    float w = wrow[m * 64];
                    acc[m][0] = fmaf(hv.x, w, acc[m][0]);
                    acc[m][1] = fmaf(hv.y, w, acc[m][1]);
                    acc[m][2] = fmaf(hv.z, w, acc[m][2]);
                    acc[m][3] = fmaf(hv.w, w, acc[m][3]);
                }
            }
#pragma unroll
            for (int m = 0; m < 7; m++) {
                float* mp = smix + m * 64 + ft;
#pragma unroll
                for (int el = 0; el < 4; el++)
                    mp[(4 * g + el) * 832] = acc[m][el] * msc;
            }
        }
        {
            float acc[6][4];
#pragma unroll
            for (int m = 0; m < 6; m++)
#pragma unroll
                for (int el = 0; el < 4; el++) acc[m][el] = 0.f;
#pragma unroll 2
            for (int f = 0; f < 64; f++) {
                float4 hv = *(const float4*)(h2 + f * 20 + 4 * g);
                const float* wrow = Wm3 + f * 832 + 7 * 64 + ft;
#pragma unroll
                for (int m = 0; m < 6; m++) {
                    float w = wrow[m * 64];
                    acc[m][0] = fmaf(hv.x, w, acc[m][0]);
                    acc[m][1] = fmaf(hv.y, w, acc[m][1]);
                    acc[m][2] = fmaf(hv.z, w, acc[m][2]);
                    acc[m][3] = fmaf(hv.w, w, acc[m][3]);
                }
            }
#pragma unroll
            for (int m = 0; m < 6; m++) {
                float* mp = smix + (7 + m) * 64 + ft;
#pragma unroll
                for (int el = 0; el < 4; el++)
                    mp[(4 * g + el) * 832] = acc[m][el] * msc;
            }
        }
    }
    __syncthreads();

    // ---- scatter: group g handles edges 4g..4g+3 ----
    for (int el = 0; el < 4; el++) {
        int e = 4 * g + el;
        if (!sact[e]) continue;
        int sn = ssend[e], rn = srecv[e];
        const float* T = sT + e * 104;
        const float* sh = ssh + e * 16;
        const float* mx = smix + e * 832 + ft;  // mx[m*64]
        float* ap = abuf + (size_t)rn * 2752;

        float s0v = g0buf[sn * 64 + ft];
        float s1v[3], s2v[5];
#pragma unroll
        for (int c = 0; c < 3; c++) s1v[c] = g1buf[sn * 192 + c * 64 + ft];
#pragma unroll
        for (int c = 0; c < 5; c++) s2v[c] = g2buf[sn * 320 + c * 64 + ft];

        // m0 -> a0 (base 0)
        atomicAdd(ap + ft, s0v * mx[0]);
        float tp110 = s1v[0] * T[0] + s1v[1] * T[1] + s1v[2] * T[2];
        atomicAdd(ap + 64 + ft, tp110 * mx[64]);
        float tp220 = 0.f;
#pragma unroll
        for (int i = 0; i < 5; i++) tp220 = fmaf(s2v[i], T[3 + i], tp220);
        atomicAdd(ap + 128 + ft, tp220 * mx[128]);

        // m1 -> a1 (base 192)
#pragma unroll
        for (int c = 0; c < 3; c++) {
            float* p = ap + 192 + c * 320;
            atomicAdd(p + ft, s1v[c] * mx[3 * 64]);
            atomicAdd(p + 64 + ft, s0v * sh[c] * mx[4 * 64]);
            float t121 = s1v[0] * T[8 + c] + s1v[1] * T[11 + c] + s1v[2] * T[14 + c];
            atomicAdd(p + 128 + ft, t121 * mx[5 * 64]);
            float t211 = 0.f, t231 = 0.f;
#pragma unroll
            for (int i = 0; i < 5; i++) {
                t211 = fmaf(s2v[i], T[17 + i * 3 + c], t211);
                t231 = fmaf(s2v[i], T[32 + i * 3 + c], t231);
            }
            atomicAdd(p + 192 + ft, t211 * mx[6 * 64]);
            atomicAdd(p + 256 + ft, t231 * mx[7 * 64]);
        }

        // m2 -> a2 (base 1152)
#pragma unroll
        for (int c = 0; c < 5; c++) {
            float* p = ap + 1152 + c * 320;
            atomicAdd(p + ft, s2v[c] * mx[8 * 64]);
            atomicAdd(p + 64 + ft, s0v * sh[3 + c] * mx[9 * 64]);
            float t112 = 0.f, t132 = 0.f;
#pragma unroll
            for (int i = 0; i < 3; i++) {
                t112 = fmaf(s1v[i], T[47 + i * 5 + c], t112);
                t132 = fmaf(s1v[i], T[62 + i * 5 + c], t132);
            }
            atomicAdd(p + 128 + ft, t112 * mx[10 * 64]);
            atomicAdd(p + 192 + ft, t132 * mx[11 * 64]);
            float t222 = 0.f;
#pragma unroll
            for (int i = 0; i < 5; i++) t222 = fmaf(s2v[i], T[77 + i * 5 + c], t222);
            atomicAdd(p + 256 + ft, t222 * mx[12 * 64]);
        }
    }
}

// ---------------- node output: 4 nodes / block, 320 threads ----------------
__global__ void __launch_bounds__(320) node_out_kernel(const float* __restrict__ Wd0,
                                const float* __restrict__ Wd1,
                                const float* __restrict__ Wd2,
                                float* __restrict__ out) {
    int n0 = blockIdx.x * 4;
    int t = threadIdx.x;  // 320 threads
    __shared__ float saT[2752 * 4];  // [j][nn] transposed accumulators
    __shared__ float sd0[4 * 192];   // swish(d0) per node

    for (int j = t; j < 2752; j += 320) {
#pragma unroll
        for (int nn = 0; nn < 4; nn++)
            saT[j * 4 + nn] = abuf[(size_t)(n0 + nn) * 2752 + j];
    }
    __syncthreads();

    // d0: 192 -> 192
    if (t < 192) {
        float a0 = 0.f, a1 = 0.f, a2 = 0.f, a3 = 0.f;
#pragma unroll 8
        for (int m = 0; m < 192; m++) {
            float w = Wd0[m * 192 + t];
            float4 av = *(const float4*)(saT + m * 4);
            a0 = fmaf(av.x, w, a0); a1 = fmaf(av.y, w, a1);
            a2 = fmaf(av.z, w, a2); a3 = fmaf(av.w, w, a3);
        }
        const float s = 0.0721687836487032f;  // 1/sqrt(192)
        sd0[0 * 192 + t] = swishf(a0 * s);
        sd0[1 * 192 + t] = swishf(a1 * s);
        sd0[2 * 192 + t] = swishf(a2 * s);
        sd0[3 * 192 + t] = swishf(a3 * s);
    }
    __syncthreads();

    if (t < 64) {
#pragma unroll
        for (int nn = 0; nn < 4; nn++)
            out[(size_t)(n0 + nn) * 576 + t] += sd0[nn * 192 + t];
    }

    const float s320 = 0.0559016994374947f;  // 1/sqrt(320)

    // d1: a1[c][320] @ Wd1[320][64], gated
    if (t < 192) {
        int c = t / 64, f = t % 64;
        float a0 = 0.f, a1 = 0.f, a2 = 0.f, a3 = 0.f;
        const float* base = saT + (192 + c * 320) * 4;
#pragma unroll 8
        for (int m = 0; m < 320; m++) {
            float w = Wd1[m * 64 + f];
            float4 av = *(const float4*)(base + m * 4);
            a0 = fmaf(av.x, w, a0); a1 = fmaf(av.y, w, a1);
            a2 = fmaf(av.z, w, a2); a3 = fmaf(av.w, w, a3);
        }
        float r[4] = {a0, a1, a2, a3};
#pragma unroll
        for (int nn = 0; nn < 4; nn++)
            out[(size_t)(n0 + nn) * 576 + 64 + f * 3 + c] += r[nn] * s320 * sd0[nn * 192 + 64 + f];
    }

    // d2: a2[c][320] @ Wd2[320][64], gated
    {
        int c = t / 64, f = t % 64;
        float a0 = 0.f, a1 = 0.f, a2 = 0.f, a3 = 0.f;
        const float* base = saT + (1152 + c * 320) * 4;
#pragma unroll 8
        for (int m = 0; m < 320; m++) {
            float w = Wd2[m * 64 + f];
            float4 av = *(const float4*)(base + m * 4);
            a0 = fmaf(av.x, w, a0); a1 = fmaf(av.y, w, a1);
            a2 = fmaf(av.z, w, a2); a3 = fmaf(av.w, w, a3);
        }
        float r[4] = {a0, a1, a2, a3};
#pragma unroll
        for (int nn = 0; nn < 4; nn++)
            out[(size_t)(n0 + nn) * 576 + 256 + f * 5 + c] += r[nn] * s320 * sd0[nn * 192 + 128 + f];
    }
}

// ---------------- launcher ----------------
extern "C" void kernel_launch(void* const* d_in, const int* in_sizes, int n_in,
                              void* d_out, int out_size) {
    const float* vectors    = (const float*)d_in[0];
    const float* node_feats = (const float*)d_in[1];
    const int*   node_specie= (const int*)d_in[2];
    const int*   senders    = (const int*)d_in[3];
    const int*   receivers  = (const int*)d_in[4];
    const float* Wsc0 = (const float*)d_in[5];
    const float* Wsc1 = (const float*)d_in[6];
    const float* Wsc2 = (const float*)d_in[7];
    const float* Wu0  = (const float*)d_in[8];
    const float* Wu1  = (const float*)d_in[9];
    const float* Wu2  = (const float*)d_in[10];
    const float* Wm1  = (const float*)d_in[11];
    const float* Wm2  = (const float*)d_in[12];
    const float* Wm3  = (const float*)d_in[13];
    const float* Wd0  = (const float*)d_in[14];
    const float* Wd1  = (const float*)d_in[15];
    const float* Wd2  = (const float*)d_in[16];
    float* out = (float*)d_out;

    const int ek_smem = EK_SMEM_FLOATS * 4;  // 71808 B
    cudaFuncSetAttribute(edge_kernel, cudaFuncAttributeMaxDynamicSharedMemorySize, ek_smem);

    cg_init_kernel<<<16, 32>>>();
    zero_acc_kernel<<<2048, 256>>>();
    node_prep_kernel<<<NNODE, 64>>>(node_feats, node_specie, Wsc0, Wsc1, Wsc2,
                                    Wu0, Wu1, Wu2, out);
    edge_kernel<<<NEDGE / 16, 256, ek_smem>>>(vectors, senders, receivers, Wm1, Wm2, Wm3);
    node_out_kernel<<<NNODE / 4, 320>>>(Wd0, Wd1, Wd2, out);
}

// round 7
// speedup vs baseline: 1.3485x; 1.0851x over previous
#include <cuda_runtime.h>
#include <cuda_bf16.h>
#include <math.h>

#define NNODE 5000
#define NEDGE 50000
#define FDIM 64

// ---------------- device scratch ----------------
__device__ float g0buf[NNODE * 64];
__device__ float g1buf[NNODE * 192];   // [n][c(3)][f(64)]
__device__ float g2buf[NNODE * 320];   // [n][c(5)][f(64)]
__device__ float abuf[NNODE * 2752];   // [n][ a0(192) | a1(960) | a2(1600) ]
__device__ float d_CG[504];

#define OFF110 0
#define OFF220 9
#define OFF121 34
#define OFF211 79
#define OFF231 124
#define OFF112 229
#define OFF132 274
#define OFF222 379

// ---------------- CG coefficient computation (exact, device-side) ----------------
__device__ __forceinline__ double dfact(int n) {
    const double F[10] = {1., 1., 2., 6., 24., 120., 720., 5040., 40320., 362880.};
    return F[n];
}

__device__ double cgc(int j1, int m1, int j2, int m2, int j3, int m3) {
    if (m1 + m2 != m3) return 0.0;
    int lo = j1 - j2; if (lo < 0) lo = -lo;
    if (j3 < lo || j3 > j1 + j2) return 0.0;
    double pref = sqrt((2.0 * j3 + 1.0) * dfact(j3 + j1 - j2) * dfact(j3 - j1 + j2) *
                       dfact(j1 + j2 - j3) / dfact(j1 + j2 + j3 + 1));
    pref *= sqrt(dfact(j3 + m3) * dfact(j3 - m3) * dfact(j1 - m1) * dfact(j1 + m1) *
                 dfact(j2 - m2) * dfact(j2 + m2));
    double s = 0.0;
    for (int k = 0; k <= j1 + j2 + j3; k++) {
        int d0 = j1 + j2 - j3 - k, d1 = j1 - m1 - k, d2 = j2 + m2 - k;
        int d3 = j3 - j2 + m1 + k, d4 = j3 - j1 - m2 + k;
        if (d0 < 0 || d1 < 0 || d2 < 0 || d3 < 0 || d4 < 0) continue;
        double term = 1.0 / (dfact(k) * dfact(d0) * dfact(d1) * dfact(d2) * dfact(d3) * dfact(d4));
        s += (k & 1) ? -term : term;
    }
    return pref * s;
}

__device__ double2 Umat(int l, int i, int a) {
    const double s = 0.70710678118654752440;
    int mi = i - l;
    if (mi == 0) return (a == l) ? make_double2(1.0, 0.0) : make_double2(0.0, 0.0);
    if (mi > 0) {
        int m = mi; double sgn = (m & 1) ? -1.0 : 1.0;
        if (a == l + m) return make_double2(sgn * s, 0.0);
        if (a == l - m) return make_double2(s, 0.0);
    } else {
        int m = -mi; double sgn = (m & 1) ? -1.0 : 1.0;
        if (a == l - m) return make_double2(0.0, s);
        if (a == l + m) return make_double2(0.0, -sgn * s);
    }
    return make_double2(0.0, 0.0);
}

__device__ float realcg(int l1, int l2, int l3, int i, int j, int k) {
    double re = 0.0;
    int d1 = 2 * l1 + 1, d2 = 2 * l2 + 1, d3 = 2 * l3 + 1;
    for (int a = 0; a < d1; a++) {
        double2 u1 = Umat(l1, i, a);
        if (u1.x == 0.0 && u1.y == 0.0) continue;
        for (int b = 0; b < d2; b++) {
            double2 u2 = Umat(l2, j, b);
            if (u2.x == 0.0 && u2.y == 0.0) continue;
            double pr = u1.x * u2.x - u1.y * u2.y;
            double pi = u1.x * u2.y + u1.y * u2.x;
            for (int c = 0; c < d3; c++) {
                double2 u3 = Umat(l3, k, c);
                u3.y = -u3.y;
                if (u3.x == 0.0 && u3.y == 0.0) continue;
                double cg = cgc(l1, a - l1, l2, b - l2, l3, c - l3);
                if (cg == 0.0) continue;
                re += (pr * u3.x - pi * u3.y) * cg;
            }
        }
    }
    return (float)re;
}

__global__ void cg_init_kernel() {
    int idx = blockIdx.x * blockDim.x + threadIdx.x;
    if (idx >= 504) return;
    int l1, l2, l3, flat;
    if (idx < 9)        { l1 = 1; l2 = 1; l3 = 0; flat = idx; }
    else if (idx < 34)  { l1 = 2; l2 = 2; l3 = 0; flat = idx - 9; }
    else if (idx < 79)  { l1 = 1; l2 = 2; l3 = 1; flat = idx - 34; }
    else if (idx < 124) { l1 = 2; l2 = 1; l3 = 1; flat = idx - 79; }
    else if (idx < 229) { l1 = 2; l2 = 3; l3 = 1; flat = idx - 124; }
    else if (idx < 274) { l1 = 1; l2 = 1; l3 = 2; flat = idx - 229; }
    else if (idx < 379) { l1 = 1; l2 = 3; l3 = 2; flat = idx - 274; }
    else                { l1 = 2; l2 = 2; l3 = 2; flat = idx - 379; }
    int dd2 = 2 * l2 + 1, dd3 = 2 * l3 + 1;
    int i = flat / (dd2 * dd3), j = (flat / dd3) % dd2, k = flat % dd3;
    d_CG[idx] = realcg(l1, l2, l3, i, j, k);
}

// ---------------- zero accumulators (vectorized) ----------------
__global__ void zero_acc_kernel() {
    float4* p = reinterpret_cast<float4*>(abuf);
    int n4 = NNODE * 2752 / 4;
    int i = blockIdx.x * blockDim.x + threadIdx.x;
    int stride = gridDim.x * blockDim.x;
    float4 z = make_float4(0.f, 0.f, 0.f, 0.f);
    for (int k = i; k < n4; k += stride) p[k] = z;
}

// ---------------- node prep: sc (-> out) and g projections ----------------
__global__ void node_prep_kernel(const float* __restrict__ nf,
                                 const int* __restrict__ specie,
                                 const float* __restrict__ Wsc0, const float* __restrict__ Wsc1,
                                 const float* __restrict__ Wsc2, const float* __restrict__ Wu0,
                                 const float* __restrict__ Wu1, const float* __restrict__ Wu2,
                                 float* __restrict__ out) {
    int n = blockIdx.x;
    int g = threadIdx.x;  // 64 threads
    __shared__ float sf[576];
    for (int i = g; i < 576; i += 64) sf[i] = nf[n * 576 + i];
    __syncthreads();
    int sp = specie[n];
    const float* w0p = Wsc0 + sp * 4096;
    const float* w1p = Wsc1 + sp * 4096;
    const float* w2p = Wsc2 + sp * 4096;

    float sc0 = 0.f, g0 = 0.f;
    float sc1[3] = {0.f, 0.f, 0.f}, g1[3] = {0.f, 0.f, 0.f};
    float sc2[5] = {0.f, 0.f, 0.f, 0.f, 0.f}, g2[5] = {0.f, 0.f, 0.f, 0.f, 0.f};
#pragma unroll 4
    for (int f = 0; f < 64; f++) {
        float w0 = w0p[f * 64 + g], u0 = Wu0[f * 64 + g];
        float w1 = w1p[f * 64 + g], u1 = Wu1[f * 64 + g];
        float w2 = w2p[f * 64 + g], u2 = Wu2[f * 64 + g];
        float v0 = sf[f];
        sc0 = fmaf(v0, w0, sc0);
        g0  = fmaf(v0, u0, g0);
#pragma unroll
        for (int c = 0; c < 3; c++) {
            float v = sf[64 + f * 3 + c];
            sc1[c] = fmaf(v, w1, sc1[c]);
            g1[c]  = fmaf(v, u1, g1[c]);
        }
#pragma unroll
        for (int c = 0; c < 5; c++) {
            float v = sf[256 + f * 5 + c];
            sc2[c] = fmaf(v, w2, sc2[c]);
            g2[c]  = fmaf(v, u2, g2[c]);
        }
    }
    const float invF = 0.125f;
    float* orow = out + (size_t)n * 576;
    orow[g] = sc0 * invF;
#pragma unroll
    for (int c = 0; c < 3; c++) orow[64 + g * 3 + c] = sc1[c] * invF;
#pragma unroll
    for (int c = 0; c < 5; c++) orow[256 + g * 5 + c] = sc2[c] * invF;
    g0buf[n * 64 + g] = g0 * invF;
#pragma unroll
    for (int c = 0; c < 3; c++) g1buf[n * 192 + c * 64 + g] = g1[c] * invF;
#pragma unroll
    for (int c = 0; c < 5; c++) g2buf[n * 320 + c * 64 + g] = g2[c] * invF;
}

__device__ __forceinline__ float swishf(float x) {
    return x / (1.0f + __expf(-x));
}

// ---------------- edge kernel: 16 edges / block, 256 threads (4 groups x 4 edges) ----
// MLP3 + scatter fused in two register-resident passes:
//   pass A: channels {0,1,3,4,5,9,10,11} (consume s0/s1 only)
//   pass B: channels {2,6,7,8,12}        (consume s2 only)
// static smem ~18.6 KB -> 4 blocks/SM (reg-capped at 64 via launch_bounds)
__global__ void __launch_bounds__(256, 4) edge_kernel(const float* __restrict__ vectors,
                            const int* __restrict__ senders,
                            const int* __restrict__ receivers,
                            const float* __restrict__ Wm1,
                            const float* __restrict__ Wm2,
                            const float* __restrict__ Wm3) {
    __shared__ float h1[64 * 20];
    __shared__ float h2[64 * 20];
    __shared__ float sT[16 * 104];
    __shared__ float ssh[16 * 16];
    __shared__ float sradT[8 * 16];
    __shared__ float sx[16], sinvx[16];
    __shared__ int ssend[16], srecv[16], sact[16];

    int t = threadIdx.x;
    int ft = t & 63;
    int g = t >> 6;       // group g handles edges 4g..4g+3
    int e0 = blockIdx.x * 16;

    // ---- geometry ----
    if (t < 16) {
        int e = e0 + t;
        float vx = vectors[e * 3 + 0], vy = vectors[e * 3 + 1], vz = vectors[e * 3 + 2];
        float x = sqrtf(fmaxf(vx * vx + vy * vy + vz * vz, 1e-12f));
        float invx = 1.0f / x;
        float ux = vx * invx, uy = vy * invx, uz = vz * invx;
        sx[t] = x; sinvx[t] = invx;
        sact[t] = (x < 1.0f) ? 1 : 0;
        ssend[t] = senders[e];
        srecv[t] = receivers[e];
        float* sh = ssh + t * 16;
        const float s3 = 1.7320508075688772f;
        const float s15 = 3.872983346207417f;
        const float s5 = 2.23606797749979f;
        const float c35 = 2.091650066335189f;
        const float c105 = 10.246950765959598f;
        const float c21 = 1.6201851746019651f;
        const float c7 = 1.3228756555322954f;
        sh[0] = s3 * uy; sh[1] = s3 * uz; sh[2] = s3 * ux;
        sh[3] = s15 * ux * uy;
        sh[4] = s15 * uy * uz;
        sh[5] = 0.5f * s5 * (3.0f * uz * uz - 1.0f);
        sh[6] = s15 * ux * uz;
        sh[7] = 0.5f * s15 * (ux * ux - uy * uy);
        sh[8]  = c35 * uy * (3.0f * ux * ux - uy * uy);
        sh[9]  = c105 * ux * uy * uz;
        sh[10] = c21 * uy * (5.0f * uz * uz - 1.0f);
        sh[11] = c7 * uz * (5.0f * uz * uz - 3.0f);
        sh[12] = c21 * ux * (5.0f * uz * uz - 1.0f);
        sh[13] = 0.5f * c105 * uz * (ux * ux - uy * uy);
        sh[14] = c35 * ux * (ux * ux - 3.0f * uy * uy);
        sh[15] = 0.f;
    }
    __syncthreads();

    // ---- radial basis ----
    if (t < 128) {
        int e = t & 15, n = t >> 4;
        float x = sx[e];
        float env = 0.f;
        if (x < 1.0f) {
            float x2 = x * x, x4 = x2 * x2, x6 = x4 * x2, x7 = x6 * x, x8 = x7 * x;
            env = 1.0f - 28.0f * x6 + 48.0f * x7 - 21.0f * x8;
        }
        float nn = (float)(n + 1);
        sradT[n * 16 + e] = 1.41421356237f * sinf(3.14159265358979f * nn * x) * sinvx[e] * env;
    }
    __syncthreads();

    // ---- contracted CG tensors: sT[e][j] = sum_j' sh[e][j'] * C[i,j',k] ----
    for (int idx = t; idx < 16 * 102; idx += 256) {
        int e = idx / 102, j = idx % 102;
        const float* sh = ssh + e * 16;
        float v = 0.f;
        if (j < 3) {
            int i = j;
            for (int q = 0; q < 3; q++) v = fmaf(sh[q], d_CG[OFF110 + i * 3 + q], v);
        } else if (j < 8) {
            int i = j - 3;
            for (int q = 0; q < 5; q++) v = fmaf(sh[3 + q], d_CG[OFF220 + i * 5 + q], v);
        } else if (j < 17) {
            int ee = j - 8; int i = ee / 3, k = ee % 3;
            for (int q = 0; q < 5; q++) v = fmaf(sh[3 + q], d_CG[OFF121 + (i * 5 + q) * 3 + k], v);
        } else if (j < 32) {
            int ee = j - 17; int i = ee / 3, k = ee % 3;
            for (int q = 0; q < 3; q++) v = fmaf(sh[q], d_CG[OFF211 + (i * 3 + q) * 3 + k], v);
        } else if (j < 47) {
            int ee = j - 32; int i = ee / 3, k = ee % 3;
            for (int q = 0; q < 7; q++) v = fmaf(sh[8 + q], d_CG[OFF231 + (i * 7 + q) * 3 + k], v);
        } else if (j < 62) {
            int ee = j - 47; int i = ee / 5, k = ee % 5;
            for (int q = 0; q < 3; q++) v = fmaf(sh[q], d_CG[OFF112 + (i * 3 + q) * 5 + k], v);
        } else if (j < 77) {
            int ee = j - 62; int i = ee / 5, k = ee % 5;
            for (int q = 0; q < 7; q++) v = fmaf(sh[8 + q], d_CG[OFF132 + (i * 7 + q) * 5 + k], v);
        } else {
            int ee = j - 77; int i = ee / 5, k = ee % 5;
            for (int q = 0; q < 5; q++) v = fmaf(sh[3 + q], d_CG[OFF222 + (i * 5 + q) * 5 + k], v);
        }
        sT[e * 104 + j] = v;
    }
    __syncthreads();

    // ---- MLP layer 1: 8 -> 64 ----
    {
        float a0 = 0.f, a1 = 0.f, a2 = 0.f, a3 = 0.f;
#pragma unroll
        for (int i = 0; i < 8; i++) {
            float w = Wm1[i * 64 + ft];
            float4 r = *(const float4*)(sradT + i * 16 + 4 * g);
            a0 = fmaf(r.x, w, a0); a1 = fmaf(r.y, w, a1);
            a2 = fmaf(r.z, w, a2); a3 = fmaf(r.w, w, a3);
        }
        const float s8 = 0.35355339059327f;
        h1[ft * 20 + 4 * g + 0] = swishf(a0 * s8);
        h1[ft * 20 + 4 * g + 1] = swishf(a1 * s8);
        h1[ft * 20 + 4 * g + 2] = swishf(a2 * s8);
        h1[ft * 20 + 4 * g + 3] = swishf(a3 * s8);
    }
    __syncthreads();

    // ---- MLP layer 2: 64 -> 64 ----
    {
        float a0 = 0.f, a1 = 0.f, a2 = 0.f, a3 = 0.f;
#pragma unroll 8
        for (int f = 0; f < 64; f++) {
            float w = Wm2[f * 64 + ft];
            float4 hv = *(const float4*)(h1 + f * 20 + 4 * g);
            a0 = fmaf(hv.x, w, a0); a1 = fmaf(hv.y, w, a1);
            a2 = fmaf(hv.z, w, a2); a3 = fmaf(hv.w, w, a3);
        }
        const float s64 = 0.125f;
        h2[ft * 20 + 4 * g + 0] = swishf(a0 * s64);
        h2[ft * 20 + 4 * g + 1] = swishf(a1 * s64);
        h2[ft * 20 + 4 * g + 2] = swishf(a2 * s64);
        h2[ft * 20 + 4 * g + 3] = swishf(a3 * s64);
    }
    __syncthreads();

    const float msc = 0.125f * 0.316227766016838f;  // /sqrt(64) * 1/sqrt(AVG)

    // ================= PASS A: channels {0,1,3,4,5,9,10,11} (s0/s1) =================
    {
        float acc[8][4];
#pragma unroll
        for (int q = 0; q < 8; q++)
#pragma unroll
            for (int el = 0; el < 4; el++) acc[q][el] = 0.f;
#pragma unroll 2
        for (int f = 0; f < 64; f++) {
            float4 hv = *(const float4*)(h2 + f * 20 + 4 * g);
            const float* wrow = Wm3 + f * 832 + ft;
            float w;
#define FMA4(Q, M)                                            \
            w = wrow[(M) * 64];                               \
            acc[Q][0] = fmaf(hv.x, w, acc[Q][0]);             \
            acc[Q][1] = fmaf(hv.y, w, acc[Q][1]);             \
            acc[Q][2] = fmaf(hv.z, w, acc[Q][2]);             \
            acc[Q][3] = fmaf(hv.w, w, acc[Q][3]);
            FMA4(0, 0) FMA4(1, 1) FMA4(2, 3) FMA4(3, 4)
            FMA4(4, 5) FMA4(5, 9) FMA4(6, 10) FMA4(7, 11)
#undef FMA4
        }
#pragma unroll
        for (int q = 0; q < 8; q++)
#pragma unroll
            for (int el = 0; el < 4; el++) acc[q][el] *= msc;

        // gather s0, s1 and scatter pass-A channels
#pragma unroll
        for (int el = 0; el < 4; el++) {
            int e = 4 * g + el;
            if (!sact[e]) continue;
            int sn = ssend[e];
            float* ap = abuf + (size_t)srecv[e] * 2752;
            const float* T = sT + e * 104;
            const float* sh = ssh + e * 16;
            float s0v = g0buf[sn * 64 + ft];
            float s1a = g1buf[sn * 192 + 0 * 64 + ft];
            float s1b = g1buf[sn * 192 + 1 * 64 + ft];
            float s1c = g1buf[sn * 192 + 2 * 64 + ft];

            // m0: a0[0:64]
            atomicAdd(ap + ft, s0v * acc[0][el]);
            // m1: a0[64:128] tp110
            float tp110 = s1a * T[0] + s1b * T[1] + s1c * T[2];
            atomicAdd(ap + 64 + ft, tp110 * acc[1][el]);
#pragma unroll
            for (int c = 0; c < 3; c++) {
                float* p = ap + 192 + c * 320;
                // m3: s1[c]
                float s1cc = (c == 0) ? s1a : ((c == 1) ? s1b : s1c);
                atomicAdd(p + ft, s1cc * acc[2][el]);
                // m4: s0*sh1[c]
                atomicAdd(p + 64 + ft, s0v * sh[c] * acc[3][el]);
                // m5: t121
                float t121 = s1a * T[8 + c] + s1b * T[11 + c] + s1c * T[14 + c];
                atomicAdd(p + 128 + ft, t121 * acc[4][el]);
            }
#pragma unroll
            for (int c = 0; c < 5; c++) {
                float* p = ap + 1152 + c * 320;
                // m9: s0*sh2[c]
                atomicAdd(p + 64 + ft, s0v * sh[3 + c] * acc[5][el]);
                // m10: t112
                float t112 = s1a * T[47 + c] + s1b * T[52 + c] + s1c * T[57 + c];
                atomicAdd(p + 128 + ft, t112 * acc[6][el]);
                // m11: t132
                float t132 = s1a * T[62 + c] + s1b * T[67 + c] + s1c * T[72 + c];
                atomicAdd(p + 192 + ft, t132 * acc[7][el]);
            }
        }
    }

    // ================= PASS B: channels {2,6,7,8,12} (s2) =================
    {
        float acc[5][4];
#pragma unroll
        for (int q = 0; q < 5; q++)
#pragma unroll
            for (int el = 0; el < 4; el++) acc[q][el] = 0.f;
#pragma unroll 2
        for (int f = 0; f < 64; f++) {
            float4 hv = *(const float4*)(h2 + f * 20 + 4 * g);
            const float* wrow = Wm3 + f * 832 + ft;
            float w;
#define FMA4(Q, M)                                            \
            w = wrow[(M) * 64];                               \
            acc[Q][0] = fmaf(hv.x, w, acc[Q][0]);             \
            acc[Q][1] = fmaf(hv.y, w, acc[Q][1]);             \
            acc[Q][2] = fmaf(hv.z, w, acc[Q][2]);             \
            acc[Q][3] = fmaf(hv.w, w, acc[Q][3]);
            FMA4(0, 2) FMA4(1, 6) FMA4(2, 7) FMA4(3, 8) FMA4(4, 12)
#undef FMA4
        }
#pragma unroll
        for (int q = 0; q < 5; q++)
#pragma unroll
            for (int el = 0; el < 4; el++) acc[q][el] *= msc;

#pragma unroll
        for (int el = 0; el < 4; el++) {
            int e = 4 * g + el;
            if (!sact[e]) continue;
            int sn = ssend[e];
            float* ap = abuf + (size_t)srecv[e] * 2752;
            const float* T = sT + e * 104;
            float s2v[5];
#pragma unroll
            for (int c = 0; c < 5; c++) s2v[c] = g2buf[sn * 320 + c * 64 + ft];

            // m2: a0[128:192] tp220
            float tp220 = 0.f;
#pragma unroll
            for (int i = 0; i < 5; i++) tp220 = fmaf(s2v[i], T[3 + i], tp220);
            atomicAdd(ap + 128 + ft, tp220 * acc[0][el]);

#pragma unroll
            for (int c = 0; c < 3; c++) {
                float* p = ap + 192 + c * 320;
                float t211 = 0.f, t231 = 0.f;
#pragma unroll
                for (int i = 0; i < 5; i++) {
                    t211 = fmaf(s2v[i], T[17 + i * 3 + c], t211);
                    t231 = fmaf(s2v[i], T[32 + i * 3 + c], t231);
                }
                // m6, m7
                atomicAdd(p + 192 + ft, t211 * acc[1][el]);
                atomicAdd(p + 256 + ft, t231 * acc[2][el]);
            }
#pragma unroll
            for (int c = 0; c < 5; c++) {
                float* p = ap + 1152 + c * 320;
                // m8: s2[c]
                atomicAdd(p + ft, s2v[c] * acc[3][el]);
                // m12: t222
                float t222 = 0.f;
#pragma unroll
                for (int i = 0; i < 5; i++) t222 = fmaf(s2v[i], T[77 + i * 5 + c], t222);
                atomicAdd(p + 256 + ft, t222 * acc[4][el]);
            }
        }
    }
}

// ---------------- node output: 4 nodes / block, 320 threads ----------------
__global__ void __launch_bounds__(320) node_out_kernel(const float* __restrict__ Wd0,
                                const float* __restrict__ Wd1,
                                const float* __restrict__ Wd2,
                                float* __restrict__ out) {
    int n0 = blockIdx.x * 4;
    int t = threadIdx.x;
    __shared__ float saT[2752 * 4];
    __shared__ float sd0[4 * 192];

    for (int j = t; j < 2752; j += 320) {
#pragma unroll
        for (int nn = 0; nn < 4; nn++)
            saT[j * 4 + nn] = abuf[(size_t)(n0 + nn) * 2752 + j];
    }
    __syncthreads();

    if (t < 192) {
        float a0 = 0.f, a1 = 0.f, a2 = 0.f, a3 = 0.f;
#pragma unroll 8
        for (int m = 0; m < 192; m++) {
            float w = Wd0[m * 192 + t];
            float4 av = *(const float4*)(saT + m * 4);
            a0 = fmaf(av.x, w, a0); a1 = fmaf(av.y, w, a1);
            a2 = fmaf(av.z, w, a2); a3 = fmaf(av.w, w, a3);
        }
        const float s = 0.0721687836487032f;
        sd0[0 * 192 + t] = swishf(a0 * s);
        sd0[1 * 192 + t] = swishf(a1 * s);
        sd0[2 * 192 + t] = swishf(a2 * s);
        sd0[3 * 192 + t] = swishf(a3 * s);
    }
    __syncthreads();

    if (t < 64) {
#pragma unroll
        for (int nn = 0; nn < 4; nn++)
            out[(size_t)(n0 + nn) * 576 + t] += sd0[nn * 192 + t];
    }

    const float s320 = 0.0559016994374947f;

    if (t < 192) {
        int c = t / 64, f = t % 64;
        float a0 = 0.f, a1 = 0.f, a2 = 0.f, a3 = 0.f;
        const float* base = saT + (192 + c * 320) * 4;
#pragma unroll 8
        for (int m = 0; m < 320; m++) {
            float w = Wd1[m * 64 + f];
            float4 av = *(const float4*)(base + m * 4);
            a0 = fmaf(av.x, w, a0); a1 = fmaf(av.y, w, a1);
            a2 = fmaf(av.z, w, a2); a3 = fmaf(av.w, w, a3);
        }
        float r[4] = {a0, a1, a2, a3};
#pragma unroll
        for (int nn = 0; nn < 4; nn++)
            out[(size_t)(n0 + nn) * 576 + 64 + f * 3 + c] += r[nn] * s320 * sd0[nn * 192 + 64 + f];
    }

    {
        int c = t / 64, f = t % 64;
        float a0 = 0.f, a1 = 0.f, a2 = 0.f, a3 = 0.f;
        const float* base = saT + (1152 + c * 320) * 4;
#pragma unroll 8
        for (int m = 0; m < 320; m++) {
            float w = Wd2[m * 64 + f];
            float4 av = *(const float4*)(base + m * 4);
            a0 = fmaf(av.x, w, a0); a1 = fmaf(av.y, w, a1);
            a2 = fmaf(av.z, w, a2); a3 = fmaf(av.w, w, a3);
        }
        float r[4] = {a0, a1, a2, a3};
#pragma unroll
        for (int nn = 0; nn < 4; nn++)
            out[(size_t)(n0 + nn) * 576 + 256 + f * 5 + c] += r[nn] * s320 * sd0[nn * 192 + 128 + f];
    }
}

// ---------------- launcher ----------------
extern "C" void kernel_launch(void* const* d_in, const int* in_sizes, int n_in,
                              void* d_out, int out_size) {
    const float* vectors    = (const float*)d_in[0];
    const float* node_feats = (const float*)d_in[1];
    const int*   node_specie= (const int*)d_in[2];
    const int*   senders    = (const int*)d_in[3];
    const int*   receivers  = (const int*)d_in[4];
    const float* Wsc0 = (const float*)d_in[5];
    const float* Wsc1 = (const float*)d_in[6];
    const float* Wsc2 = (const float*)d_in[7];
    const float* Wu0  = (const float*)d_in[8];
    const float* Wu1  = (const float*)d_in[9];
    const float* Wu2  = (const float*)d_in[10];
    const float* Wm1  = (const float*)d_in[11];
    const float* Wm2  = (const float*)d_in[12];
    const float* Wm3  = (const float*)d_in[13];
    const float* Wd0  = (const float*)d_in[14];
    const float* Wd1  = (const float*)d_in[15];
    const float* Wd2  = (const float*)d_in[16];
    float* out = (float*)d_out;

    cg_init_kernel<<<16, 32>>>();
    zero_acc_kernel<<<2048, 256>>>();
    node_prep_kernel<<<NNODE, 64>>>(node_feats, node_specie, Wsc0, Wsc1, Wsc2,
                                    Wu0, Wu1, Wu2, out);
    edge_kernel<<<NEDGE / 16, 256>>>(vectors, senders, receivers, Wm1, Wm2, Wm3);
    node_out_kernel<<<NNODE / 4, 320>>>(Wd0, Wd1, Wd2, out);
}